// round 17
// baseline (speedup 1.0000x reference)
#include <cuda_runtime.h>
#include <cuda_bf16.h>

// Fused blocked affine-scan RK4 integrator, v13 (tail-compressed v8).
// x_{t+1} = A x_t + B u_t exactly. L=16, 256 chunks/block, 25 blocks, 1 launch.
//   v8 base + (a) lane-parallel block prefix (ladder over (M^256)^(2^k) +
//   butterfly sum; powers built in the barrier spin window) and (b) per-warp
//   epilogue store (warp-private smem columns + contiguous 4KB output span
//   per warp -> __syncwarp only; final block sync removed).

#define L_CHUNK 16
#define CPB 256
#define NWARP (CPB / 32)
#define F4_PER_CHUNK (L_CHUNK / 2)
#define MAX_BLOCKS 32     // lane-parallel prefix requires nblocks <= 32

__device__ float4 g_bt[MAX_BLOCKS];        // per-block total drive
__device__ volatile unsigned g_sense = 0;  // monotonically increasing epoch
__device__ unsigned g_count = 0;           // arrival counter (self-resetting)

// ---------------------------------------------------------------------------
// fp32 RK4 step mirroring the reference arithmetic (basis probing only)
// ---------------------------------------------------------------------------
struct FSys { float Cm[4], Km[4], Md[2], dt; };

__device__ __forceinline__ FSys mksys(const float* M, const float* C,
                                      const float* K, const float* dtp) {
    FSys m;
    m.Md[0] = M[0]; m.Md[1] = M[1];
    float C0 = C[0], C1 = C[1], C2 = C[2];
    m.Cm[0] = C0 + C1; m.Cm[1] = -C1; m.Cm[2] = -C1; m.Cm[3] = C2 + C1;
    float K0 = K[0], K1 = K[1], K2 = K[2];
    m.Km[0] = K0 + K1; m.Km[1] = -K1; m.Km[2] = -K1; m.Km[3] = K2 + K1;
    m.dt = dtp[0];
    return m;
}

__device__ void fstep(const FSys& m, float s[4], float u0, float u1) {
    float dt = m.dt;
    float y0 = s[0], y1 = s[1], v0 = s[2], v1 = s[3];
#define ACC(z0, z1, w0, w1, a0, a1)                                             \
    a0 = (u0 - (m.Cm[0]*(w0) + m.Cm[1]*(w1)) - (m.Km[0]*(z0) + m.Km[1]*(z1))) / m.Md[0]; \
    a1 = (u1 - (m.Cm[2]*(w0) + m.Cm[3]*(w1)) - (m.Km[2]*(z0) + m.Km[3]*(z1))) / m.Md[1];
    float k1a, k1b; ACC(y0, y1, v0, v1, k1a, k1b);
    float y2a = y0 + v0*dt*0.5f, y2b = y1 + v1*dt*0.5f;
    float v2a = v0 + k1a*dt*0.5f, v2b = v1 + k1b*dt*0.5f;
    float k2a, k2b; ACC(y2a, y2b, v2a, v2b, k2a, k2b);
    float y3a = y0 + v2a*dt*0.5f, y3b = y1 + v2b*dt*0.5f;
    float v3a = v0 + k2a*dt*0.5f, v3b = v1 + k2b*dt*0.5f;
    float k3a, k3b; ACC(y3a, y3b, v3a, v3b, k3a, k3b);
    float y4a = y0 + v3a*dt, y4b = y1 + v3b*dt;
    float v4a = v0 + k3a*dt, v4b = v1 + k3b*dt;
    float k4a, k4b; ACC(y4a, y4b, v4a, v4b, k4a, k4b);
    (void)y2a; (void)y2b; (void)y3a; (void)y3b; (void)y4a; (void)y4b;
    s[0] = y0 + dt/6.f * (v0 + 2.f*v2a + 2.f*v3a + v4a);
    s[1] = y1 + dt/6.f * (v1 + 2.f*v2b + 2.f*v3b + v4b);
    s[2] = v0 + dt/6.f * (k1a + 2.f*k2a + 2.f*k3a + k4a);
    s[3] = v1 + dt/6.f * (k1b + 2.f*k2b + 2.f*k3b + k4b);
#undef ACC
}

__device__ __forceinline__ void probe_AB(float* sA, float* sB,
                                         const float* M, const float* C,
                                         const float* K, const float* dtp, int t) {
    if (t < 4) {
        FSys m = mksys(M, C, K, dtp);
        float s[4] = {0.f, 0.f, 0.f, 0.f}; s[t] = 1.f;
        fstep(m, s, 0.f, 0.f);
        sA[0*4 + t] = s[0]; sA[1*4 + t] = s[1]; sA[2*4 + t] = s[2]; sA[3*4 + t] = s[3];
    } else if (t < 6) {
        FSys m = mksys(M, C, K, dtp);
        int j = t - 4;
        float s[4] = {0.f, 0.f, 0.f, 0.f};
        fstep(m, s, j == 0 ? 1.f : 0.f, j == 1 ? 1.f : 0.f);
        sB[0*2 + j] = s[0]; sB[1*2 + j] = s[1]; sB[2*2 + j] = s[2]; sB[3*2 + j] = s[3];
    }
}

// ---------------------------------------------------------------------------
// MATVEC4(Am, d..., x...): x <- Am * x + d   (d is the ADDITIVE term!)
// ---------------------------------------------------------------------------
#define MATVEC4(Am, d0, d1, d2, d3, x0_, x1_, x2_, x3_)                        \
    do {                                                                       \
        float n0 = fmaf((Am)[0],  (x0_), (Am)[1]  * (x1_)) +                   \
                   fmaf((Am)[2],  (x2_), fmaf((Am)[3],  (x3_), (d0)));         \
        float n1 = fmaf((Am)[4],  (x0_), (Am)[5]  * (x1_)) +                   \
                   fmaf((Am)[6],  (x2_), fmaf((Am)[7],  (x3_), (d1)));         \
        float n2 = fmaf((Am)[8],  (x0_), (Am)[9]  * (x1_)) +                   \
                   fmaf((Am)[10], (x2_), fmaf((Am)[11], (x3_), (d2)));         \
        float n3 = fmaf((Am)[12], (x0_), (Am)[13] * (x1_)) +                   \
                   fmaf((Am)[14], (x2_), fmaf((Am)[15], (x3_), (d3)));         \
        (x0_) = n0; (x1_) = n1; (x2_) = n2; (x3_) = n3;                        \
    } while (0)

// v <- Mat * v + b
#define AFFINE_F4(Mat, v, b)                                                   \
    do {                                                                       \
        float t0 = (v).x, t1 = (v).y, t2 = (v).z, t3 = (v).w;                  \
        MATVEC4(Mat, (b).x, (b).y, (b).z, (b).w, t0, t1, t2, t3);              \
        (v).x = t0; (v).y = t1; (v).z = t2; (v).w = t3;                        \
    } while (0)

// Cooperative 4x4 matmul (lanes 0..15 of warp 0)
__device__ __forceinline__ void coop_mm(float* R, const float* Pm, const float* Qm, int t) {
    if (t < 16) {
        int i = t >> 2, j = t & 3;
        R[t] = fmaf(Pm[i*4+0], Qm[0*4+j],
               fmaf(Pm[i*4+1], Qm[1*4+j],
               fmaf(Pm[i*4+2], Qm[2*4+j],
                    Pm[i*4+3] * Qm[3*4+j])));
    }
    __syncwarp();
}

// ---------------------------------------------------------------------------
// Fused kernel
// ---------------------------------------------------------------------------
__global__ void __launch_bounds__(CPB, 1)
fused_kernel(const float4* __restrict__ u4, float4* __restrict__ out4,
             const float* __restrict__ M, const float* __restrict__ C,
             const float* __restrict__ K, const float* __restrict__ x0in,
             const float* __restrict__ dtp,
             int nf4, int nblocks) {
    __shared__ float sA[16], sB[8];
    __shared__ float sMp[5][16];      // M^1..M^16  (M = A^16)
    __shared__ float sM32[16];        // M^32 (warp stride)
    __shared__ float sBP[5][16];      // (M^256)^(2^k), k=0..4
    __shared__ float sT1[16], sT2[16];
    __shared__ float sX0[4];
    __shared__ float4 s_w[NWARP];     // warp totals
    __shared__ float4 s_Sw[NWARP];    // warp start states
    __shared__ float2 s_u[L_CHUNK][CPB + 2];

    int tid = threadIdx.x;
    int lane = tid & 31;
    int wrp = tid >> 5;
    int c0 = blockIdx.x * CPB;

    probe_AB(sA, sB, M, C, K, dtp, tid);
    if (tid == 6) {   // x0 layout [y1,v1,y2,v2] -> state [y1,y2,v1,v2]
        sX0[0] = x0in[0]; sX0[1] = x0in[2]; sX0[2] = x0in[1]; sX0[3] = x0in[3];
    }

    // ---- stage u tile: 2048 contiguous float4 -> transposed smem -------------
#pragma unroll
    for (int k = 0; k < 8; k++) {
        int idx = tid + CPB * k;
        int g4 = c0 * F4_PER_CHUNK + idx;
        float4 qv = (g4 < nf4) ? u4[g4] : make_float4(0.f, 0.f, 0.f, 0.f);
        int cc = idx >> 3, j = idx & 7;
        s_u[2*j][cc]     = make_float2(qv.x, qv.y);
        s_u[2*j + 1][cc] = make_float2(qv.z, qv.w);
    }
    __syncthreads();

    // ---- warp 0: pre-scan power table M^1..M^16, M^32 -------------------------
    if (wrp == 0) {
        if (lane < 16) sT1[lane] = sA[lane];
        __syncwarp();
        coop_mm(sT2, sT1, sT1, lane);                    // A^2
        coop_mm(sT1, sT2, sT2, lane);                    // A^4
        coop_mm(sT2, sT1, sT1, lane);                    // A^8
        coop_mm(sMp[0], sT2, sT2, lane);                 // A^16 = M
        coop_mm(sMp[1], sMp[0], sMp[0], lane);           // M^2
        coop_mm(sMp[2], sMp[1], sMp[1], lane);           // M^4
        coop_mm(sMp[3], sMp[2], sMp[2], lane);           // M^8
        coop_mm(sMp[4], sMp[3], sMp[3], lane);           // M^16
        coop_mm(sM32,   sMp[4], sMp[4], lane);           // M^32
    }

    float A[16], B[8];
#pragma unroll
    for (int i = 0; i < 16; i++) A[i] = sA[i];
#pragma unroll
    for (int i = 0; i < 8; i++) B[i] = sB[i];

    // ---- per-lane chunk drive (zero IC) --------------------------------------
    float d0 = 0.f, d1 = 0.f, d2 = 0.f, d3 = 0.f;
#pragma unroll
    for (int i = 0; i < L_CHUNK; i++) {
        float2 uu = s_u[i][tid];
        float w0 = fmaf(B[0], uu.x, B[1] * uu.y);
        float w1 = fmaf(B[2], uu.x, B[3] * uu.y);
        float w2 = fmaf(B[4], uu.x, B[5] * uu.y);
        float w3 = fmaf(B[6], uu.x, B[7] * uu.y);
        MATVEC4(A, w0, w1, w2, w3, d0, d1, d2, d3);
    }
    __syncthreads();   // pre-scan power table ready for all warps

    // ---- warp Kogge-Stone inclusive affine scan over lanes -------------------
    float4 e = make_float4(d0, d1, d2, d3);
#pragma unroll
    for (int k = 0; k < 5; k++) {
        int off = 1 << k;
        float4 p;
        p.x = __shfl_up_sync(0xffffffffu, e.x, off);
        p.y = __shfl_up_sync(0xffffffffu, e.y, off);
        p.z = __shfl_up_sync(0xffffffffu, e.z, off);
        p.w = __shfl_up_sync(0xffffffffu, e.w, off);
        if (lane >= off) {
            float t0 = p.x, t1 = p.y, t2 = p.z, t3 = p.w;
            MATVEC4(sMp[k], e.x, e.y, e.z, e.w, t0, t1, t2, t3);  // t = M^2^k * p + e
            e = make_float4(t0, t1, t2, t3);
        }
    }
    if (lane == 31) s_w[wrp] = e;      // warp totals
    __syncthreads();

    // ---- publish block total; arrive; build block powers in the spin window --
    unsigned sense0 = 0;
    if (tid == 0) {
        float4 bt = s_w[0];
#pragma unroll
        for (int w = 1; w < NWARP; w++)
            AFFINE_F4(sM32, bt, s_w[w]);   // bt = M^32 * bt + W_w
        g_bt[blockIdx.x] = bt;
        __threadfence();
        sense0 = g_sense;
        unsigned my = atomicAdd(&g_count, 1);
        if (my == (unsigned)nblocks - 1) {
            g_count = 0;
            __threadfence();
            g_sense = sense0 + 1;
        }
    }
    if (wrp == 0) {    // overlapped with the barrier wait
        coop_mm(sT1,    sM32,   sM32,   lane);   // M^64
        coop_mm(sT2,    sT1,    sT1,    lane);   // M^128
        coop_mm(sBP[0], sT2,    sT2,    lane);   // M^256
        coop_mm(sBP[1], sBP[0], sBP[0], lane);   // M^512
        coop_mm(sBP[2], sBP[1], sBP[1], lane);   // M^1024
        coop_mm(sBP[3], sBP[2], sBP[2], lane);   // M^2048
        coop_mm(sBP[4], sBP[3], sBP[3], lane);   // M^4096
    }
    if (tid == 0) {
        while (g_sense == sense0) { }
    }
    __syncthreads();   // all blocks' E_* published and visible

    // ---- warp 0: lane-parallel prefix over block totals -----------------------
    // S = (M^256)^myb * X0 + sum_{j<myb} (M^256)^(myb-1-j) * E_j
    int myb = blockIdx.x;
    if (wrp == 0) {
        float4 v = make_float4(0.f, 0.f, 0.f, 0.f);
        int expn = 0;
        if (lane < myb) {
            v = __ldcg(&g_bt[lane]);
            expn = myb - 1 - lane;
        } else if (lane == myb) {
            v = make_float4(sX0[0], sX0[1], sX0[2], sX0[3]);
            expn = myb;
        }
#pragma unroll
        for (int k = 0; k < 5; k++) {
            if ((expn >> k) & 1) {
                float t0 = v.x, t1 = v.y, t2 = v.z, t3 = v.w;
                MATVEC4(sBP[k], 0.f, 0.f, 0.f, 0.f, t0, t1, t2, t3);
                v = make_float4(t0, t1, t2, t3);
            }
        }
#pragma unroll
        for (int off = 16; off >= 1; off >>= 1) {   // butterfly sum
            v.x += __shfl_xor_sync(0xffffffffu, v.x, off);
            v.y += __shfl_xor_sync(0xffffffffu, v.y, off);
            v.z += __shfl_xor_sync(0xffffffffu, v.z, off);
            v.w += __shfl_xor_sync(0xffffffffu, v.w, off);
        }
        if (lane == 0) {
            float4 S = v;
#pragma unroll
            for (int w = 0; w < NWARP; w++) {
                s_Sw[w] = S;
                AFFINE_F4(sM32, S, s_w[w]);   // Sw_{w+1} = M^32 * Sw_w + W_w
            }
        }
    }
    __syncthreads();

    // exclusive prefix of lane drives
    float4 eprev;
    eprev.x = __shfl_up_sync(0xffffffffu, e.x, 1);
    eprev.y = __shfl_up_sync(0xffffffffu, e.y, 1);
    eprev.z = __shfl_up_sync(0xffffffffu, e.z, 1);
    eprev.w = __shfl_up_sync(0xffffffffu, e.w, 1);
    if (lane == 0) eprev = make_float4(0.f, 0.f, 0.f, 0.f);

    // ladder: v <- M^(2^k) * v for each set bit of lane
    float4 v = s_Sw[wrp];
#pragma unroll
    for (int k = 0; k < 5; k++) {
        if ((lane >> k) & 1) {
            float t0 = v.x, t1 = v.y, t2 = v.z, t3 = v.w;
            MATVEC4(sMp[k], 0.f, 0.f, 0.f, 0.f, t0, t1, t2, t3);  // t = M^2^k * v
            v = make_float4(t0, t1, t2, t3);
        }
    }
    // this lane's chunk start state = M^lane * Sw + eprev
    float x0 = v.x + eprev.x, x1 = v.y + eprev.y;
    float x2 = v.z + eprev.z, x3 = v.w + eprev.w;

    // ---- replay 16 steps, write positions back into the tile -----------------
#pragma unroll
    for (int i = 0; i < L_CHUNK; i++) {
        float2 uu = s_u[i][tid];
        float w0 = fmaf(B[0], uu.x, B[1] * uu.y);
        float w1 = fmaf(B[2], uu.x, B[3] * uu.y);
        float w2 = fmaf(B[4], uu.x, B[5] * uu.y);
        float w3 = fmaf(B[6], uu.x, B[7] * uu.y);
        MATVEC4(A, w0, w1, w2, w3, x0, x1, x2, x3);
        s_u[i][tid] = make_float2(x0, x1);
    }

    // ---- per-warp epilogue store: warp-private columns, contiguous 4KB span --
    // warp w owns chunks [32w, 32w+32): smem columns it alone wrote above,
    // and output float4 range [(c0+32w)*8, (c0+32w)*8 + 256).
    __syncwarp();
    int wbase4 = (c0 + (wrp << 5)) * F4_PER_CHUNK;   // warp's first output float4
#pragma unroll
    for (int k = 0; k < 8; k++) {
        int idx = lane + 32 * k;          // 0..255 within warp region
        int g4 = wbase4 + idx;
        if (g4 < nf4) {
            int cc = (wrp << 5) + (idx >> 3), j = idx & 7;
            float2 a = s_u[2*j][cc];
            float2 b = s_u[2*j + 1][cc];
            out4[g4] = make_float4(a.x, a.y, b.x, b.y);
        }
    }
}

// ---------------------------------------------------------------------------
// Launch
// ---------------------------------------------------------------------------
extern "C" void kernel_launch(void* const* d_in, const int* in_sizes, int n_in,
                              void* d_out, int out_size) {
    const float* u  = (const float*)d_in[0];
    const float* M  = (const float*)d_in[1];
    const float* C  = (const float*)d_in[2];
    const float* K  = (const float*)d_in[3];
    const float* x0 = (const float*)d_in[4];
    const float* dt = (const float*)d_in[5];

    int T   = in_sizes[0] / 2;
    int NC  = (T + L_CHUNK - 1) / L_CHUNK;
    int nf4 = (2 * T) / 4;
    int nb  = (NC + CPB - 1) / CPB;   // 25 blocks for T=100000 — co-resident

    fused_kernel<<<nb, CPB>>>((const float4*)u, (float4*)d_out,
                              M, C, K, x0, dt, nf4, nb);
}